// round 6
// baseline (speedup 1.0000x reference)
#include <cuda_runtime.h>
#include <cuda_fp16.h>
#include <math_constants.h>
#include <cstdint>

#define N_NODES 100000
#define D_MODEL 256
#define N_SLOTS 512
#define TILE_M 64
#define THREADS 256
#define N_TILES ((N_NODES + TILE_M - 1) / TILE_M)   // 1563

// smem byte offsets
#define OFF_QH 0          // 32KB  (GEMM1 A hi)
#define OFF_QL 32768      // 32KB  (GEMM1 A lo)
#define OFF_PH 0          // 64KB  (GEMM2 A hi only — overlays QH+QL)
#define OFF_PMAX 65536    // 2KB [64][8]
#define OFF_PSUM 67584    // 2KB
#define SMEM_BYTES 69632

// Pre-packed B fragments for mma.sync.m16n8k16.row.col (4 halfs per lane, uint2).
// G1B[mem][split][kt(16)][nt(64)][lane(32)]  : B = M^T  (k=dmodel, n=slot)
// G2B[mem][split][kt(32)][nt(32)][lane(32)]  : B = M    (k=slot,  n=dmodel)
__device__ __align__(16) uint2 G1B[2][2][16][64][32];
__device__ __align__(16) uint2 G2B[2][2][32][32][32];

__device__ __forceinline__ void split2h(float x, float y, uint32_t& hi, uint32_t& lo) {
    __half hx = __float2half_rn(x);
    __half hy = __float2half_rn(y);
    __half lx = __float2half_rn(x - __half2float(hx));
    __half ly = __float2half_rn(y - __half2float(hy));
    __half2 h = __halves2half2(hx, hy);
    __half2 l = __halves2half2(lx, ly);
    hi = *(uint32_t*)&h;
    lo = *(uint32_t*)&l;
}

__device__ __forceinline__ uint32_t pack2h(float x, float y) {
    __half2 h = __halves2half2(__float2half_rn(x), __float2half_rn(y));
    return *(uint32_t*)&h;
}

__device__ __forceinline__ void mma16816(float* c, const uint4& a, const uint2& b) {
    asm volatile(
        "mma.sync.aligned.m16n8k16.row.col.f32.f16.f16.f32 "
        "{%0,%1,%2,%3}, {%4,%5,%6,%7}, {%8,%9}, {%0,%1,%2,%3};"
        : "+f"(c[0]), "+f"(c[1]), "+f"(c[2]), "+f"(c[3])
        : "r"(a.x), "r"(a.y), "r"(a.z), "r"(a.w), "r"(b.x), "r"(b.y));
}

// ---------------- prep: pack memory matrices into B-fragment order ----------------
__global__ void prep_kernel(const float* __restrict__ ma, const float* __restrict__ ms) {
    int idx = blockIdx.x * blockDim.x + threadIdx.x;
    if (idx >= 131072) return;
    bool isG2 = idx >= 65536;
    int r = idx & 65535;
    int lane = r & 31;
    int t = lane & 3, g = lane >> 2;
    if (!isG2) {
        int nt = (r >> 5) & 63;
        int kt = (r >> 11) & 15;
        int mem = (r >> 15) & 1;
        const float* src = mem ? ms : ma;
        int slot = nt * 8 + g;
        int k = kt * 16 + 2 * t;
        float v0 = src[slot * D_MODEL + k];
        float v1 = src[slot * D_MODEL + k + 1];
        float v2 = src[slot * D_MODEL + k + 8];
        float v3 = src[slot * D_MODEL + k + 9];
        uint32_t h01, l01, h23, l23;
        split2h(v0, v1, h01, l01);
        split2h(v2, v3, h23, l23);
        G1B[mem][0][kt][nt][lane] = make_uint2(h01, h23);
        G1B[mem][1][kt][nt][lane] = make_uint2(l01, l23);
    } else {
        int nt = (r >> 5) & 31;
        int kt = (r >> 10) & 31;
        int mem = (r >> 15) & 1;
        const float* src = mem ? ms : ma;
        int col = nt * 8 + g;
        int ks = kt * 16 + 2 * t;
        float v0 = src[(ks)     * D_MODEL + col];
        float v1 = src[(ks + 1) * D_MODEL + col];
        float v2 = src[(ks + 8) * D_MODEL + col];
        float v3 = src[(ks + 9) * D_MODEL + col];
        uint32_t h01, l01, h23, l23;
        split2h(v0, v1, h01, l01);
        split2h(v2, v3, h23, l23);
        G2B[mem][0][kt][nt][lane] = make_uint2(h01, h23);
        G2B[mem][1][kt][nt][lane] = make_uint2(l01, l23);
    }
}

// ---------------- main fused kernel ----------------
__global__ __launch_bounds__(THREADS, 1)
void smgt_hmma(const float* __restrict__ query, float* __restrict__ out) {
    extern __shared__ char smem[];
    const int tid = threadIdx.x;
    const int w = tid >> 5, lane = tid & 31;
    const int t = lane & 3, g = lane >> 2;
    const int memi = blockIdx.y;
    const int n0 = blockIdx.x * TILE_M;
    float* __restrict__ outg = out + (size_t)memi * N_NODES * 512u;

    // ---- load Q tile, split fp16 hi/lo, store in A-fragment-packed layout ----
    #pragma unroll 4
    for (int it = 0; it < 16; it++) {
        int idx = tid + it * THREADS;    // 0..4095 float4s
        int rr = idx >> 6;               // row 0..63
        int c4 = idx & 63;
        int gr = n0 + rr;
        float4 v = make_float4(0.f, 0.f, 0.f, 0.f);
        if (gr < N_NODES) v = ((const float4*)query)[(size_t)gr * 64 + c4];
        int mt = rr >> 4, sr = rr & 15, gg = sr & 7, hr = sr >> 3;
        #pragma unroll
        for (int p = 0; p < 2; p++) {
            int k = c4 * 4 + 2 * p;
            int kt = k >> 4, sk = k & 15;
            int ln = gg * 4 + ((sk & 7) >> 1);
            int off = ((kt * 4 + mt) * 32 + (ln ^ (kt & 7))) * 16 + 4 * hr + 8 * (sk >> 3);
            float x = p ? v.z : v.x;
            float y = p ? v.w : v.y;
            uint32_t hi, lo;
            split2h(x, y, hi, lo);
            *(uint32_t*)(smem + OFF_QH + off) = hi;
            *(uint32_t*)(smem + OFF_QL + off) = lo;
        }
    }
    __syncthreads();

    // ================= GEMM1: S = Q @ M^T (64x512, warp = 64x64) =================
    float acc[4][8][4];
    #pragma unroll
    for (int mt = 0; mt < 4; mt++)
        #pragma unroll
        for (int j = 0; j < 8; j++)
            #pragma unroll
            for (int i = 0; i < 4; i++) acc[mt][j][i] = 0.f;

    {
        const uint2* __restrict__ g1h = &G1B[memi][0][0][w * 8][0];
        const uint2* __restrict__ g1l = &G1B[memi][1][0][w * 8][0];
        // element (kt, h, j): kt*2048 + (h*4+j)*32 + lane   (uint2 units)
        uint2 bh[2][4], bl[2][4];
        #pragma unroll
        for (int j = 0; j < 4; j++) {
            bh[0][j] = g1h[j * 32 + lane];
            bl[0][j] = g1l[j * 32 + lane];
        }

        #pragma unroll 1
        for (int kt = 0; kt < 16; kt++) {
            uint4 ah[4], al[4];
            #pragma unroll
            for (int mt = 0; mt < 4; mt++) {
                int chunk = ((kt * 4 + mt) * 32 + (lane ^ (kt & 7))) * 16;
                ah[mt] = *(const uint4*)(smem + OFF_QH + chunk);
                al[mt] = *(const uint4*)(smem + OFF_QL + chunk);
            }

            // ---- half h=0: prefetch (kt, h=1) -> buf1, compute buf0 (term-major) ----
            {
                int base = kt * 2048 + 128 + lane;
                #pragma unroll
                for (int j = 0; j < 4; j++) {
                    bh[1][j] = g1h[base + j * 32];
                    bl[1][j] = g1l[base + j * 32];
                }
                // term 1: ah*bh  (16 independent accs)
                #pragma unroll
                for (int j = 0; j < 4; j++)
                    #pragma unroll
                    for (int mt = 0; mt < 4; mt++)
                        mma16816(acc[mt][j], ah[mt], bh[0][j]);
                // term 2: al*bh
                #pragma unroll
                for (int j = 0; j < 4; j++)
                    #pragma unroll
                    for (int mt = 0; mt < 4; mt++)
                        mma16816(acc[mt][j], al[mt], bh[0][j]);
                // term 3: ah*bl
                #pragma unroll
                for (int j = 0; j < 4; j++)
                    #pragma unroll
                    for (int mt = 0; mt < 4; mt++)
                        mma16816(acc[mt][j], ah[mt], bl[0][j]);
            }
            // ---- half h=1: prefetch (kt+1, h=0) -> buf0, compute buf1 (term-major) ----
            {
                if (kt + 1 < 16) {
                    int base = (kt + 1) * 2048 + lane;
                    #pragma unroll
                    for (int j = 0; j < 4; j++) {
                        bh[0][j] = g1h[base + j * 32];
                        bl[0][j] = g1l[base + j * 32];
                    }
                }
                #pragma unroll
                for (int j = 0; j < 4; j++)
                    #pragma unroll
                    for (int mt = 0; mt < 4; mt++)
                        mma16816(acc[mt][4 + j], ah[mt], bh[1][j]);
                #pragma unroll
                for (int j = 0; j < 4; j++)
                    #pragma unroll
                    for (int mt = 0; mt < 4; mt++)
                        mma16816(acc[mt][4 + j], al[mt], bh[1][j]);
                #pragma unroll
                for (int j = 0; j < 4; j++)
                    #pragma unroll
                    for (int mt = 0; mt < 4; mt++)
                        mma16816(acc[mt][4 + j], ah[mt], bl[1][j]);
            }
        }
    }

    // ================= softmax over 512 cols (accums hold S) =================
    float* pmax = (float*)(smem + OFF_PMAX);
    float* psum = (float*)(smem + OFF_PSUM);

    #pragma unroll
    for (int mt = 0; mt < 4; mt++)
        #pragma unroll
        for (int i2 = 0; i2 < 2; i2++) {
            float m = -CUDART_INF_F;
            #pragma unroll
            for (int j = 0; j < 8; j++) {
                m = fmaxf(m, acc[mt][j][2 * i2]);
                m = fmaxf(m, acc[mt][j][2 * i2 + 1]);
            }
            m = fmaxf(m, __shfl_xor_sync(0xffffffffu, m, 1));
            m = fmaxf(m, __shfl_xor_sync(0xffffffffu, m, 2));
            if (t == 0) pmax[(mt * 16 + g + 8 * i2) * 8 + w] = m;
        }
    __syncthreads();

    float gmax[4][2];
    #pragma unroll
    for (int mt = 0; mt < 4; mt++)
        #pragma unroll
        for (int i2 = 0; i2 < 2; i2++) {
            int row = mt * 16 + g + 8 * i2;
            float m = pmax[row * 8];
            #pragma unroll
            for (int j = 1; j < 8; j++) m = fmaxf(m, pmax[row * 8 + j]);
            gmax[mt][i2] = m;
        }

    #pragma unroll
    for (int mt = 0; mt < 4; mt++)
        #pragma unroll
        for (int i2 = 0; i2 < 2; i2++) {
            float s = 0.f;
            #pragma unroll
            for (int j = 0; j < 8; j++) {
                float e0 = __expf(acc[mt][j][2 * i2]     - gmax[mt][i2]);
                float e1 = __expf(acc[mt][j][2 * i2 + 1] - gmax[mt][i2]);
                acc[mt][j][2 * i2]     = e0;
                acc[mt][j][2 * i2 + 1] = e1;
                s += e0 + e1;
            }
            s += __shfl_xor_sync(0xffffffffu, s, 1);
            s += __shfl_xor_sync(0xffffffffu, s, 2);
            if (t == 0) psum[(mt * 16 + g + 8 * i2) * 8 + w] = s;
        }
    __syncthreads();

    float inv[4][2];
    #pragma unroll
    for (int mt = 0; mt < 4; mt++)
        #pragma unroll
        for (int i2 = 0; i2 < 2; i2++) {
            int row = mt * 16 + g + 8 * i2;
            float s = psum[row * 8];
            #pragma unroll
            for (int j = 1; j < 8; j++) s += psum[row * 8 + j];
            inv[mt][i2] = 1.f / (s * 16384.f);
        }

    // ---- pack P hi only (scaled by 2^14) into GEMM2 A layout (overwrites Q) ----
    #pragma unroll
    for (int mt = 0; mt < 4; mt++)
        #pragma unroll
        for (int j = 0; j < 8; j++) {
            int kt2 = w * 4 + (j >> 1);
            int base = ((kt2 * 4 + mt) * 32 + (lane ^ (kt2 & 7))) * 16 + 8 * (j & 1);
            *(uint32_t*)(smem + OFF_PH + base)     = pack2h(acc[mt][j][0] * 16384.f,
                                                            acc[mt][j][1] * 16384.f);
            *(uint32_t*)(smem + OFF_PH + base + 4) = pack2h(acc[mt][j][2] * 16384.f,
                                                            acc[mt][j][3] * 16384.f);
        }
    __syncthreads();

    // ================= GEMM2: R = P @ M (64x256, warp = 64x32, 2-term) =================
    float a2[4][4][4];
    #pragma unroll
    for (int mt = 0; mt < 4; mt++)
        #pragma unroll
        for (int j = 0; j < 4; j++)
            #pragma unroll
            for (int i = 0; i < 4; i++) a2[mt][j][i] = 0.f;

    {
        const uint2* __restrict__ g2h = &G2B[memi][0][0][w * 4][0];
        const uint2* __restrict__ g2l = &G2B[memi][1][0][w * 4][0];
        // element (kt, j): kt*1024 + j*32 + lane
        uint2 ch[2][4], cl[2][4];
        #pragma unroll
        for (int j = 0; j < 4; j++) {
            ch[0][j] = g2h[j * 32 + lane];
            cl[0][j] = g2l[j * 32 + lane];
        }

        #pragma unroll 1
        for (int kp = 0; kp < 16; kp++) {
            // ---- kt = 2*kp (buf0), prefetch kt+1 -> buf1 ----
            {
                int kt = 2 * kp;
                uint4 ph[4];
                #pragma unroll
                for (int mt = 0; mt < 4; mt++) {
                    int chunk = ((kt * 4 + mt) * 32 + (lane ^ (kt & 7))) * 16;
                    ph[mt] = *(const uint4*)(smem + OFF_PH + chunk);
                }
                int base = (kt + 1) * 1024 + lane;
                #pragma unroll
                for (int j = 0; j < 4; j++) {
                    ch[1][j] = g2h[base + j * 32];
                    cl[1][j] = g2l[base + j * 32];
                }
                #pragma unroll
                for (int j = 0; j < 4; j++)
                    #pragma unroll
                    for (int mt = 0; mt < 4; mt++)
                        mma16816(a2[mt][j], ph[mt], ch[0][j]);
                #pragma unroll
                for (int j = 0; j < 4; j++)
                    #pragma unroll
                    for (int mt = 0; mt < 4; mt++)
                        mma16816(a2[mt][j], ph[mt], cl[0][j]);
            }
            // ---- kt = 2*kp+1 (buf1), prefetch kt+1 -> buf0 ----
            {
                int kt = 2 * kp + 1;
                uint4 ph[4];
                #pragma unroll
                for (int mt = 0; mt < 4; mt++) {
                    int chunk = ((kt * 4 + mt) * 32 + (lane ^ (kt & 7))) * 16;
                    ph[mt] = *(const uint4*)(smem + OFF_PH + chunk);
                }
                if (kt + 1 < 32) {
                    int base = (kt + 1) * 1024 + lane;
                    #pragma unroll
                    for (int j = 0; j < 4; j++) {
                        ch[0][j] = g2h[base + j * 32];
                        cl[0][j] = g2l[base + j * 32];
                    }
                }
                #pragma unroll
                for (int j = 0; j < 4; j++)
                    #pragma unroll
                    for (int mt = 0; mt < 4; mt++)
                        mma16816(a2[mt][j], ph[mt], ch[1][j]);
                #pragma unroll
                for (int j = 0; j < 4; j++)
                    #pragma unroll
                    for (int mt = 0; mt < 4; mt++)
                        mma16816(a2[mt][j], ph[mt], cl[1][j]);
            }
        }
    }

    // ---- epilogue: scale by 1/(sum*2^14), store R half ----
    #pragma unroll
    for (int mt = 0; mt < 4; mt++)
        #pragma unroll
        for (int j = 0; j < 4; j++) {
            int col = w * 32 + j * 8 + 2 * t;
            #pragma unroll
            for (int i2 = 0; i2 < 2; i2++) {
                int gr = n0 + mt * 16 + g + 8 * i2;
                if (gr < N_NODES) {
                    float2 o;
                    o.x = a2[mt][j][2 * i2]     * inv[mt][i2];
                    o.y = a2[mt][j][2 * i2 + 1] * inv[mt][i2];
                    *(float2*)&outg[(size_t)gr * 512 + 256 + col] = o;
                }
            }
        }

    // ---- Q copy half ----
    #pragma unroll 4
    for (int it = 0; it < 16; it++) {
        int idx = tid + it * THREADS;
        int rr = idx >> 6, c4 = idx & 63;
        int gr = n0 + rr;
        if (gr < N_NODES)
            ((float4*)outg)[(size_t)gr * 128 + c4] = ((const float4*)query)[(size_t)gr * 64 + c4];
    }
}

extern "C" void kernel_launch(void* const* d_in, const int* in_sizes, int n_in,
                              void* d_out, int out_size) {
    const float* query      = (const float*)d_in[0];
    const float* mem_attr   = (const float*)d_in[1];
    const float* mem_struct = (const float*)d_in[2];
    float* out = (float*)d_out;

    prep_kernel<<<512, 256>>>(mem_attr, mem_struct);

    cudaFuncSetAttribute(smgt_hmma, cudaFuncAttributeMaxDynamicSharedMemorySize, SMEM_BYTES);
    dim3 grid(N_TILES, 2);
    smgt_hmma<<<grid, THREADS, SMEM_BYTES>>>(query, out);
}

// round 7
// speedup vs baseline: 1.2044x; 1.2044x over previous
#include <cuda_runtime.h>
#include <cuda_fp16.h>
#include <math_constants.h>
#include <cstdint>

#define N_NODES 100000
#define D_MODEL 256
#define N_SLOTS 512
#define TILE_M 32
#define THREADS 256
#define N_TILES (N_NODES / TILE_M)   // 3125 exactly

// smem byte offsets
#define OFF_QH 0          // 16KB  (GEMM1 A hi)
#define OFF_QL 16384      // 16KB  (GEMM1 A lo)
#define OFF_PH 0          // 32KB  (GEMM2 A hi — overlays QH+QL)
#define OFF_PMAX 32768    // 1KB [32][8]
#define OFF_PSUM 33792    // 1KB
#define SMEM_BYTES 34816

// Pre-packed B fragments for mma.sync.m16n8k16.row.col (4 halfs per lane, uint2).
// G1B[mem][split][kt(16)][nt(64)][lane(32)]  : B = M^T  (k=dmodel, n=slot)
// G2B[mem][split][kt(32)][nt(32)][lane(32)]  : B = M    (k=slot,  n=dmodel)
__device__ __align__(16) uint2 G1B[2][2][16][64][32];
__device__ __align__(16) uint2 G2B[2][2][32][32][32];

__device__ __forceinline__ void split2h(float x, float y, uint32_t& hi, uint32_t& lo) {
    __half hx = __float2half_rn(x);
    __half hy = __float2half_rn(y);
    __half lx = __float2half_rn(x - __half2float(hx));
    __half ly = __float2half_rn(y - __half2float(hy));
    __half2 h = __halves2half2(hx, hy);
    __half2 l = __halves2half2(lx, ly);
    hi = *(uint32_t*)&h;
    lo = *(uint32_t*)&l;
}

__device__ __forceinline__ uint32_t pack2h(float x, float y) {
    __half2 h = __halves2half2(__float2half_rn(x), __float2half_rn(y));
    return *(uint32_t*)&h;
}

__device__ __forceinline__ void mma16816(float* c, const uint4& a, const uint2& b) {
    asm volatile(
        "mma.sync.aligned.m16n8k16.row.col.f32.f16.f16.f32 "
        "{%0,%1,%2,%3}, {%4,%5,%6,%7}, {%8,%9}, {%0,%1,%2,%3};"
        : "+f"(c[0]), "+f"(c[1]), "+f"(c[2]), "+f"(c[3])
        : "r"(a.x), "r"(a.y), "r"(a.z), "r"(a.w), "r"(b.x), "r"(b.y));
}

// ---------------- prep: pack memory matrices into B-fragment order ----------------
__global__ void prep_kernel(const float* __restrict__ ma, const float* __restrict__ ms) {
    int idx = blockIdx.x * blockDim.x + threadIdx.x;
    if (idx >= 131072) return;
    bool isG2 = idx >= 65536;
    int r = idx & 65535;
    int lane = r & 31;
    int t = lane & 3, g = lane >> 2;
    if (!isG2) {
        int nt = (r >> 5) & 63;
        int kt = (r >> 11) & 15;
        int mem = (r >> 15) & 1;
        const float* src = mem ? ms : ma;
        int slot = nt * 8 + g;
        int k = kt * 16 + 2 * t;
        float v0 = src[slot * D_MODEL + k];
        float v1 = src[slot * D_MODEL + k + 1];
        float v2 = src[slot * D_MODEL + k + 8];
        float v3 = src[slot * D_MODEL + k + 9];
        uint32_t h01, l01, h23, l23;
        split2h(v0, v1, h01, l01);
        split2h(v2, v3, h23, l23);
        G1B[mem][0][kt][nt][lane] = make_uint2(h01, h23);
        G1B[mem][1][kt][nt][lane] = make_uint2(l01, l23);
    } else {
        int nt = (r >> 5) & 31;
        int kt = (r >> 10) & 31;
        int mem = (r >> 15) & 1;
        const float* src = mem ? ms : ma;
        int col = nt * 8 + g;
        int ks = kt * 16 + 2 * t;
        float v0 = src[(ks)     * D_MODEL + col];
        float v1 = src[(ks + 1) * D_MODEL + col];
        float v2 = src[(ks + 8) * D_MODEL + col];
        float v3 = src[(ks + 9) * D_MODEL + col];
        uint32_t h01, l01, h23, l23;
        split2h(v0, v1, h01, l01);
        split2h(v2, v3, h23, l23);
        G2B[mem][0][kt][nt][lane] = make_uint2(h01, h23);
        G2B[mem][1][kt][nt][lane] = make_uint2(l01, l23);
    }
}

// ---------------- main fused kernel (2 CTAs/SM) ----------------
__global__ __launch_bounds__(THREADS, 2)
void smgt_hmma(const float* __restrict__ query, float* __restrict__ out) {
    extern __shared__ char smem[];
    const int tid = threadIdx.x;
    const int w = tid >> 5, lane = tid & 31;
    const int t = lane & 3, g = lane >> 2;
    const int memi = blockIdx.y;
    const int n0 = blockIdx.x * TILE_M;
    float* __restrict__ outg = out + (size_t)memi * N_NODES * 512u;

    // ---- load Q tile, split fp16 hi/lo, store A-fragment-packed; fuse Q-copy out ----
    #pragma unroll 4
    for (int it = 0; it < 8; it++) {
        int idx = tid + it * THREADS;    // 0..2047 float4s
        int rr = idx >> 6;               // row 0..31
        int c4 = idx & 63;
        int gr = n0 + rr;                // always < N_NODES (3125*32 = 100000)
        float4 v = ((const float4*)query)[(size_t)gr * 64 + c4];
        ((float4*)outg)[(size_t)gr * 128 + c4] = v;   // Q copy half of output
        int mt = rr >> 4, sr = rr & 15, gg = sr & 7, hr = sr >> 3;
        #pragma unroll
        for (int p = 0; p < 2; p++) {
            int k = c4 * 4 + 2 * p;
            int kt = k >> 4, sk = k & 15;
            int ln = gg * 4 + ((sk & 7) >> 1);
            int off = ((kt * 2 + mt) * 32 + (ln ^ (kt & 7))) * 16 + 4 * hr + 8 * (sk >> 3);
            float x = p ? v.z : v.x;
            float y = p ? v.w : v.y;
            uint32_t hi, lo;
            split2h(x, y, hi, lo);
            *(uint32_t*)(smem + OFF_QH + off) = hi;
            *(uint32_t*)(smem + OFF_QL + off) = lo;
        }
    }
    __syncthreads();

    // ================= GEMM1: S = Q @ M^T (32x512, warp = 32x64) =================
    float acc[2][8][4];
    #pragma unroll
    for (int mt = 0; mt < 2; mt++)
        #pragma unroll
        for (int j = 0; j < 8; j++)
            #pragma unroll
            for (int i = 0; i < 4; i++) acc[mt][j][i] = 0.f;

    {
        const uint2* __restrict__ g1h = &G1B[memi][0][0][w * 8][0];
        const uint2* __restrict__ g1l = &G1B[memi][1][0][w * 8][0];
        // element (kt, h, j): kt*2048 + (h*4+j)*32 + lane   (uint2 units)
        uint2 bh[2][4], bl[2][4];
        #pragma unroll
        for (int j = 0; j < 4; j++) {
            bh[0][j] = g1h[j * 32 + lane];
            bl[0][j] = g1l[j * 32 + lane];
        }

        #pragma unroll 1
        for (int kt = 0; kt < 16; kt++) {
            uint4 ah[2], al[2];
            #pragma unroll
            for (int mt = 0; mt < 2; mt++) {
                int chunk = ((kt * 2 + mt) * 32 + (lane ^ (kt & 7))) * 16;
                ah[mt] = *(const uint4*)(smem + OFF_QH + chunk);
                al[mt] = *(const uint4*)(smem + OFF_QL + chunk);
            }

            // ---- half h=0: prefetch (kt, h=1) -> buf1, compute buf0 ----
            {
                int base = kt * 2048 + 128 + lane;
                #pragma unroll
                for (int j = 0; j < 4; j++) {
                    bh[1][j] = g1h[base + j * 32];
                    bl[1][j] = g1l[base + j * 32];
                }
                #pragma unroll
                for (int j = 0; j < 4; j++)
                    #pragma unroll
                    for (int mt = 0; mt < 2; mt++) {
                        mma16816(acc[mt][j], ah[mt], bh[0][j]);
                        mma16816(acc[mt][j], al[mt], bh[0][j]);
                        mma16816(acc[mt][j], ah[mt], bl[0][j]);
                    }
            }
            // ---- half h=1: prefetch (kt+1, h=0) -> buf0, compute buf1 ----
            {
                if (kt + 1 < 16) {
                    int base = (kt + 1) * 2048 + lane;
                    #pragma unroll
                    for (int j = 0; j < 4; j++) {
                        bh[0][j] = g1h[base + j * 32];
                        bl[0][j] = g1l[base + j * 32];
                    }
                }
                #pragma unroll
                for (int j = 0; j < 4; j++)
                    #pragma unroll
                    for (int mt = 0; mt < 2; mt++) {
                        mma16816(acc[mt][4 + j], ah[mt], bh[1][j]);
                        mma16816(acc[mt][4 + j], al[mt], bh[1][j]);
                        mma16816(acc[mt][4 + j], ah[mt], bl[1][j]);
                    }
            }
        }
    }

    // ================= softmax over 512 cols (accums hold S) =================
    float* pmax = (float*)(smem + OFF_PMAX);
    float* psum = (float*)(smem + OFF_PSUM);

    #pragma unroll
    for (int mt = 0; mt < 2; mt++)
        #pragma unroll
        for (int i2 = 0; i2 < 2; i2++) {
            float m = -CUDART_INF_F;
            #pragma unroll
            for (int j = 0; j < 8; j++) {
                m = fmaxf(m, acc[mt][j][2 * i2]);
                m = fmaxf(m, acc[mt][j][2 * i2 + 1]);
            }
            m = fmaxf(m, __shfl_xor_sync(0xffffffffu, m, 1));
            m = fmaxf(m, __shfl_xor_sync(0xffffffffu, m, 2));
            if (t == 0) pmax[(mt * 16 + g + 8 * i2) * 8 + w] = m;
        }
    __syncthreads();

    float gmax[2][2];
    #pragma unroll
    for (int mt = 0; mt < 2; mt++)
        #pragma unroll
        for (int i2 = 0; i2 < 2; i2++) {
            int row = mt * 16 + g + 8 * i2;
            float m = pmax[row * 8];
            #pragma unroll
            for (int j = 1; j < 8; j++) m = fmaxf(m, pmax[row * 8 + j]);
            gmax[mt][i2] = m;
        }

    #pragma unroll
    for (int mt = 0; mt < 2; mt++)
        #pragma unroll
        for (int i2 = 0; i2 < 2; i2++) {
            float s = 0.f;
            #pragma unroll
            for (int j = 0; j < 8; j++) {
                float e0 = __expf(acc[mt][j][2 * i2]     - gmax[mt][i2]);
                float e1 = __expf(acc[mt][j][2 * i2 + 1] - gmax[mt][i2]);
                acc[mt][j][2 * i2]     = e0;
                acc[mt][j][2 * i2 + 1] = e1;
                s += e0 + e1;
            }
            s += __shfl_xor_sync(0xffffffffu, s, 1);
            s += __shfl_xor_sync(0xffffffffu, s, 2);
            if (t == 0) psum[(mt * 16 + g + 8 * i2) * 8 + w] = s;
        }
    __syncthreads();

    float inv[2][2];
    #pragma unroll
    for (int mt = 0; mt < 2; mt++)
        #pragma unroll
        for (int i2 = 0; i2 < 2; i2++) {
            int row = mt * 16 + g + 8 * i2;
            float s = psum[row * 8];
            #pragma unroll
            for (int j = 1; j < 8; j++) s += psum[row * 8 + j];
            inv[mt][i2] = 1.f / (s * 16384.f);
        }

    // ---- pack P hi only (scaled by 2^14) into GEMM2 A layout (overwrites Q) ----
    #pragma unroll
    for (int mt = 0; mt < 2; mt++)
        #pragma unroll
        for (int j = 0; j < 8; j++) {
            int kt2 = w * 4 + (j >> 1);
            int base = ((kt2 * 2 + mt) * 32 + (lane ^ (kt2 & 7))) * 16 + 8 * (j & 1);
            *(uint32_t*)(smem + OFF_PH + base)     = pack2h(acc[mt][j][0] * 16384.f,
                                                            acc[mt][j][1] * 16384.f);
            *(uint32_t*)(smem + OFF_PH + base + 4) = pack2h(acc[mt][j][2] * 16384.f,
                                                            acc[mt][j][3] * 16384.f);
        }
    __syncthreads();

    // ================= GEMM2: R = P @ M (32x256, warp = 32x32, 2-term) =================
    float a2[2][4][4];
    #pragma unroll
    for (int mt = 0; mt < 2; mt++)
        #pragma unroll
        for (int j = 0; j < 4; j++)
            #pragma unroll
            for (int i = 0; i < 4; i++) a2[mt][j][i] = 0.f;

    {
        const uint2* __restrict__ g2h = &G2B[memi][0][0][w * 4][0];
        const uint2* __restrict__ g2l = &G2B[memi][1][0][w * 4][0];
        // element (kt, j): kt*1024 + j*32 + lane
        uint2 ch[2][4], cl[2][4];
        #pragma unroll
        for (int j = 0; j < 4; j++) {
            ch[0][j] = g2h[j * 32 + lane];
            cl[0][j] = g2l[j * 32 + lane];
        }

        #pragma unroll 1
        for (int kp = 0; kp < 16; kp++) {
            // ---- kt = 2*kp (buf0), prefetch kt+1 -> buf1 ----
            {
                int kt = 2 * kp;
                uint4 ph[2];
                #pragma unroll
                for (int mt = 0; mt < 2; mt++) {
                    int chunk = ((kt * 2 + mt) * 32 + (lane ^ (kt & 7))) * 16;
                    ph[mt] = *(const uint4*)(smem + OFF_PH + chunk);
                }
                int base = (kt + 1) * 1024 + lane;
                #pragma unroll
                for (int j = 0; j < 4; j++) {
                    ch[1][j] = g2h[base + j * 32];
                    cl[1][j] = g2l[base + j * 32];
                }
                #pragma unroll
                for (int j = 0; j < 4; j++)
                    #pragma unroll
                    for (int mt = 0; mt < 2; mt++) {
                        mma16816(a2[mt][j], ph[mt], ch[0][j]);
                        mma16816(a2[mt][j], ph[mt], cl[0][j]);
                    }
            }
            // ---- kt = 2*kp+1 (buf1), prefetch kt+1 -> buf0 ----
            {
                int kt = 2 * kp + 1;
                uint4 ph[2];
                #pragma unroll
                for (int mt = 0; mt < 2; mt++) {
                    int chunk = ((kt * 2 + mt) * 32 + (lane ^ (kt & 7))) * 16;
                    ph[mt] = *(const uint4*)(smem + OFF_PH + chunk);
                }
                if (kt + 1 < 32) {
                    int base = (kt + 1) * 1024 + lane;
                    #pragma unroll
                    for (int j = 0; j < 4; j++) {
                        ch[0][j] = g2h[base + j * 32];
                        cl[0][j] = g2l[base + j * 32];
                    }
                }
                #pragma unroll
                for (int j = 0; j < 4; j++)
                    #pragma unroll
                    for (int mt = 0; mt < 2; mt++) {
                        mma16816(a2[mt][j], ph[mt], ch[1][j]);
                        mma16816(a2[mt][j], ph[mt], cl[1][j]);
                    }
            }
        }
    }

    // ---- epilogue: scale by 1/(sum*2^14), store R half ----
    #pragma unroll
    for (int mt = 0; mt < 2; mt++)
        #pragma unroll
        for (int j = 0; j < 4; j++) {
            int col = w * 32 + j * 8 + 2 * t;
            #pragma unroll
            for (int i2 = 0; i2 < 2; i2++) {
                int gr = n0 + mt * 16 + g + 8 * i2;
                float2 o;
                o.x = a2[mt][j][2 * i2]     * inv[mt][i2];
                o.y = a2[mt][j][2 * i2 + 1] * inv[mt][i2];
                *(float2*)&outg[(size_t)gr * 512 + 256 + col] = o;
            }
        }
}

extern "C" void kernel_launch(void* const* d_in, const int* in_sizes, int n_in,
                              void* d_out, int out_size) {
    const float* query      = (const float*)d_in[0];
    const float* mem_attr   = (const float*)d_in[1];
    const float* mem_struct = (const float*)d_in[2];
    float* out = (float*)d_out;

    prep_kernel<<<512, 256>>>(mem_attr, mem_struct);

    cudaFuncSetAttribute(smgt_hmma, cudaFuncAttributeMaxDynamicSharedMemorySize, SMEM_BYTES);
    dim3 grid(N_TILES, 2);
    smgt_hmma<<<grid, THREADS, SMEM_BYTES>>>(query, out);
}

// round 8
// speedup vs baseline: 1.4333x; 1.1900x over previous
#include <cuda_runtime.h>
#include <cuda_fp16.h>
#include <math_constants.h>
#include <cstdint>

#define N_NODES 100000
#define D_MODEL 256
#define N_SLOTS 512
#define TILE_M 32
#define THREADS 256
#define N_TILES (N_NODES / TILE_M)   // 3125 exactly

// smem byte offsets
#define OFF_QH 0          // 16KB  (GEMM1 A hi)
#define OFF_QL 16384      // 16KB  (GEMM1 A lo)
#define OFF_PH 0          // 32KB  (GEMM2 A hi — overlays QH+QL)
#define OFF_PMAX 32768    // 1KB [32][8]
#define OFF_PSUM 33792    // 1KB
#define SMEM_BYTES 34816

// Pre-packed B fragments for mma.sync.m16n8k16.row.col (4 halfs per lane, uint2).
// G1B[mem][split][kt(16)][nt(64)][lane(32)]  : B = M^T  (k=dmodel, n=slot)
// G2B[mem][kt(32)][nt(32)][lane(32)]         : B = M hi (k=slot,  n=dmodel)
__device__ __align__(16) uint2 G1B[2][2][16][64][32];
__device__ __align__(16) uint2 G2B[2][32][32][32];

__device__ __forceinline__ void split2h(float x, float y, uint32_t& hi, uint32_t& lo) {
    __half hx = __float2half_rn(x);
    __half hy = __float2half_rn(y);
    __half lx = __float2half_rn(x - __half2float(hx));
    __half ly = __float2half_rn(y - __half2float(hy));
    __half2 h = __halves2half2(hx, hy);
    __half2 l = __halves2half2(lx, ly);
    hi = *(uint32_t*)&h;
    lo = *(uint32_t*)&l;
}

__device__ __forceinline__ uint32_t pack2h(float x, float y) {
    __half2 h = __halves2half2(__float2half_rn(x), __float2half_rn(y));
    return *(uint32_t*)&h;
}

__device__ __forceinline__ void mma16816(float* c, const uint4& a, const uint2& b) {
    asm volatile(
        "mma.sync.aligned.m16n8k16.row.col.f32.f16.f16.f32 "
        "{%0,%1,%2,%3}, {%4,%5,%6,%7}, {%8,%9}, {%0,%1,%2,%3};"
        : "+f"(c[0]), "+f"(c[1]), "+f"(c[2]), "+f"(c[3])
        : "r"(a.x), "r"(a.y), "r"(a.z), "r"(a.w), "r"(b.x), "r"(b.y));
}

// ---------------- prep: pack memory matrices into B-fragment order ----------------
__global__ void prep_kernel(const float* __restrict__ ma, const float* __restrict__ ms) {
    int idx = blockIdx.x * blockDim.x + threadIdx.x;
    if (idx >= 131072) return;
    bool isG2 = idx >= 65536;
    int r = idx & 65535;
    int lane = r & 31;
    int t = lane & 3, g = lane >> 2;
    if (!isG2) {
        int nt = (r >> 5) & 63;
        int kt = (r >> 11) & 15;
        int mem = (r >> 15) & 1;
        const float* src = mem ? ms : ma;
        int slot = nt * 8 + g;
        int k = kt * 16 + 2 * t;
        float v0 = src[slot * D_MODEL + k];
        float v1 = src[slot * D_MODEL + k + 1];
        float v2 = src[slot * D_MODEL + k + 8];
        float v3 = src[slot * D_MODEL + k + 9];
        uint32_t h01, l01, h23, l23;
        split2h(v0, v1, h01, l01);
        split2h(v2, v3, h23, l23);
        G1B[mem][0][kt][nt][lane] = make_uint2(h01, h23);
        G1B[mem][1][kt][nt][lane] = make_uint2(l01, l23);
    } else {
        int nt = (r >> 5) & 31;
        int kt = (r >> 10) & 31;
        int mem = (r >> 15) & 1;
        const float* src = mem ? ms : ma;
        int col = nt * 8 + g;
        int ks = kt * 16 + 2 * t;
        float v0 = src[(ks)     * D_MODEL + col];
        float v1 = src[(ks + 1) * D_MODEL + col];
        float v2 = src[(ks + 8) * D_MODEL + col];
        float v3 = src[(ks + 9) * D_MODEL + col];
        G2B[mem][kt][nt][lane] = make_uint2(pack2h(v0, v1), pack2h(v2, v3));
    }
}

// ---------------- main fused kernel (2 CTAs/SM) ----------------
__global__ __launch_bounds__(THREADS, 2)
void smgt_hmma(const float* __restrict__ query, float* __restrict__ out) {
    extern __shared__ char smem[];
    const int tid = threadIdx.x;
    const int w = tid >> 5, lane = tid & 31;
    const int t = lane & 3, g = lane >> 2;
    const int memi = blockIdx.y;
    const int n0 = blockIdx.x * TILE_M;
    float* __restrict__ outg = out + (size_t)memi * N_NODES * 512u;

    // ---- load Q tile, split fp16 hi/lo, store A-fragment-packed; fuse Q-copy out ----
    #pragma unroll 4
    for (int it = 0; it < 8; it++) {
        int idx = tid + it * THREADS;    // 0..2047 float4s
        int rr = idx >> 6;               // row 0..31
        int c4 = idx & 63;
        int gr = n0 + rr;                // always < N_NODES (3125*32 = 100000)
        float4 v = ((const float4*)query)[(size_t)gr * 64 + c4];
        ((float4*)outg)[(size_t)gr * 128 + c4] = v;   // Q copy half of output
        int mt = rr >> 4, sr = rr & 15, gg = sr & 7, hr = sr >> 3;
        #pragma unroll
        for (int p = 0; p < 2; p++) {
            int k = c4 * 4 + 2 * p;
            int kt = k >> 4, sk = k & 15;
            int ln = gg * 4 + ((sk & 7) >> 1);
            int off = ((kt * 2 + mt) * 32 + (ln ^ (kt & 7))) * 16 + 4 * hr + 8 * (sk >> 3);
            float x = p ? v.z : v.x;
            float y = p ? v.w : v.y;
            uint32_t hi, lo;
            split2h(x, y, hi, lo);
            *(uint32_t*)(smem + OFF_QH + off) = hi;
            *(uint32_t*)(smem + OFF_QL + off) = lo;
        }
    }
    __syncthreads();

    // ================= GEMM1: S = Q @ M^T (32x512, warp = 32x64) =================
    float acc[2][8][4];
    #pragma unroll
    for (int mt = 0; mt < 2; mt++)
        #pragma unroll
        for (int j = 0; j < 8; j++)
            #pragma unroll
            for (int i = 0; i < 4; i++) acc[mt][j][i] = 0.f;

    {
        const uint2* __restrict__ g1h = &G1B[memi][0][0][w * 8][0];
        const uint2* __restrict__ g1l = &G1B[memi][1][0][w * 8][0];
        // element (kt, h, j): kt*2048 + (h*4+j)*32 + lane   (uint2 units)
        uint2 bh[2][4], bl[2][4];
        #pragma unroll
        for (int j = 0; j < 4; j++) {
            bh[0][j] = g1h[j * 32 + lane];
            bl[0][j] = g1l[j * 32 + lane];
        }

        #pragma unroll 1
        for (int kt = 0; kt < 16; kt++) {
            uint4 ah[2], al[2];
            #pragma unroll
            for (int mt = 0; mt < 2; mt++) {
                int chunk = ((kt * 2 + mt) * 32 + (lane ^ (kt & 7))) * 16;
                ah[mt] = *(const uint4*)(smem + OFF_QH + chunk);
                al[mt] = *(const uint4*)(smem + OFF_QL + chunk);
            }

            // ---- half h=0: prefetch (kt, h=1) -> buf1, compute buf0 ----
            {
                int base = kt * 2048 + 128 + lane;
                #pragma unroll
                for (int j = 0; j < 4; j++) {
                    bh[1][j] = g1h[base + j * 32];
                    bl[1][j] = g1l[base + j * 32];
                }
                #pragma unroll
                for (int j = 0; j < 4; j++)
                    #pragma unroll
                    for (int mt = 0; mt < 2; mt++) {
                        mma16816(acc[mt][j], ah[mt], bh[0][j]);
                        mma16816(acc[mt][j], al[mt], bh[0][j]);
                        mma16816(acc[mt][j], ah[mt], bl[0][j]);
                    }
            }
            // ---- half h=1: prefetch (kt+1, h=0) -> buf0, compute buf1 ----
            {
                if (kt + 1 < 16) {
                    int base = (kt + 1) * 2048 + lane;
                    #pragma unroll
                    for (int j = 0; j < 4; j++) {
                        bh[0][j] = g1h[base + j * 32];
                        bl[0][j] = g1l[base + j * 32];
                    }
                }
                #pragma unroll
                for (int j = 0; j < 4; j++)
                    #pragma unroll
                    for (int mt = 0; mt < 2; mt++) {
                        mma16816(acc[mt][4 + j], ah[mt], bh[1][j]);
                        mma16816(acc[mt][4 + j], al[mt], bh[1][j]);
                        mma16816(acc[mt][4 + j], ah[mt], bl[1][j]);
                    }
            }
        }
    }

    // ================= softmax over 512 cols (accums hold S) =================
    float* pmax = (float*)(smem + OFF_PMAX);
    float* psum = (float*)(smem + OFF_PSUM);

    #pragma unroll
    for (int mt = 0; mt < 2; mt++)
        #pragma unroll
        for (int i2 = 0; i2 < 2; i2++) {
            float m = -CUDART_INF_F;
            #pragma unroll
            for (int j = 0; j < 8; j++) {
                m = fmaxf(m, acc[mt][j][2 * i2]);
                m = fmaxf(m, acc[mt][j][2 * i2 + 1]);
            }
            m = fmaxf(m, __shfl_xor_sync(0xffffffffu, m, 1));
            m = fmaxf(m, __shfl_xor_sync(0xffffffffu, m, 2));
            if (t == 0) pmax[(mt * 16 + g + 8 * i2) * 8 + w] = m;
        }
    __syncthreads();

    float gmax[2][2];
    #pragma unroll
    for (int mt = 0; mt < 2; mt++)
        #pragma unroll
        for (int i2 = 0; i2 < 2; i2++) {
            int row = mt * 16 + g + 8 * i2;
            float m = pmax[row * 8];
            #pragma unroll
            for (int j = 1; j < 8; j++) m = fmaxf(m, pmax[row * 8 + j]);
            gmax[mt][i2] = m;
        }

    #pragma unroll
    for (int mt = 0; mt < 2; mt++)
        #pragma unroll
        for (int i2 = 0; i2 < 2; i2++) {
            float s = 0.f;
            #pragma unroll
            for (int j = 0; j < 8; j++) {
                float e0 = __expf(acc[mt][j][2 * i2]     - gmax[mt][i2]);
                float e1 = __expf(acc[mt][j][2 * i2 + 1] - gmax[mt][i2]);
                acc[mt][j][2 * i2]     = e0;
                acc[mt][j][2 * i2 + 1] = e1;
                s += e0 + e1;
            }
            s += __shfl_xor_sync(0xffffffffu, s, 1);
            s += __shfl_xor_sync(0xffffffffu, s, 2);
            if (t == 0) psum[(mt * 16 + g + 8 * i2) * 8 + w] = s;
        }
    __syncthreads();

    float inv[2][2];
    #pragma unroll
    for (int mt = 0; mt < 2; mt++)
        #pragma unroll
        for (int i2 = 0; i2 < 2; i2++) {
            int row = mt * 16 + g + 8 * i2;
            float s = psum[row * 8];
            #pragma unroll
            for (int j = 1; j < 8; j++) s += psum[row * 8 + j];
            inv[mt][i2] = 1.f / (s * 16384.f);
        }

    // ---- pack P hi only (scaled by 2^14) into GEMM2 A layout (overwrites Q) ----
    #pragma unroll
    for (int mt = 0; mt < 2; mt++)
        #pragma unroll
        for (int j = 0; j < 8; j++) {
            int kt2 = w * 4 + (j >> 1);
            int base = ((kt2 * 2 + mt) * 32 + (lane ^ (kt2 & 7))) * 16 + 8 * (j & 1);
            *(uint32_t*)(smem + OFF_PH + base)     = pack2h(acc[mt][j][0] * 16384.f,
                                                            acc[mt][j][1] * 16384.f);
            *(uint32_t*)(smem + OFF_PH + base + 4) = pack2h(acc[mt][j][2] * 16384.f,
                                                            acc[mt][j][3] * 16384.f);
        }
    __syncthreads();

    // ================= GEMM2: R = P @ M (32x256, warp = 32x32, 1-term) =================
    float a2[2][4][4];
    #pragma unroll
    for (int mt = 0; mt < 2; mt++)
        #pragma unroll
        for (int j = 0; j < 4; j++)
            #pragma unroll
            for (int i = 0; i < 4; i++) a2[mt][j][i] = 0.f;

    {
        const uint2* __restrict__ g2h = &G2B[memi][0][w * 4][0];
        // element (kt, j): kt*1024 + j*32 + lane
        uint2 ch[2][4];
        #pragma unroll
        for (int j = 0; j < 4; j++) ch[0][j] = g2h[j * 32 + lane];

        #pragma unroll 1
        for (int kp = 0; kp < 16; kp++) {
            // ---- kt = 2*kp (buf0), prefetch kt+1 -> buf1 ----
            {
                int kt = 2 * kp;
                uint4 ph[2];
                #pragma unroll
                for (int mt = 0; mt < 2; mt++) {
                    int chunk = ((kt * 2 + mt) * 32 + (lane ^ (kt & 7))) * 16;
                    ph[mt] = *(const uint4*)(smem + OFF_PH + chunk);
                }
                int base = (kt + 1) * 1024 + lane;
                #pragma unroll
                for (int j = 0; j < 4; j++) ch[1][j] = g2h[base + j * 32];
                #pragma unroll
                for (int j = 0; j < 4; j++)
                    #pragma unroll
                    for (int mt = 0; mt < 2; mt++)
                        mma16816(a2[mt][j], ph[mt], ch[0][j]);
            }
            // ---- kt = 2*kp+1 (buf1), prefetch kt+1 -> buf0 ----
            {
                int kt = 2 * kp + 1;
                uint4 ph[2];
                #pragma unroll
                for (int mt = 0; mt < 2; mt++) {
                    int chunk = ((kt * 2 + mt) * 32 + (lane ^ (kt & 7))) * 16;
                    ph[mt] = *(const uint4*)(smem + OFF_PH + chunk);
                }
                if (kt + 1 < 32) {
                    int base = (kt + 1) * 1024 + lane;
                    #pragma unroll
                    for (int j = 0; j < 4; j++) ch[0][j] = g2h[base + j * 32];
                }
                #pragma unroll
                for (int j = 0; j < 4; j++)
                    #pragma unroll
                    for (int mt = 0; mt < 2; mt++)
                        mma16816(a2[mt][j], ph[mt], ch[1][j]);
            }
        }
    }

    // ---- epilogue: scale by 1/(sum*2^14), store R half ----
    #pragma unroll
    for (int mt = 0; mt < 2; mt++)
        #pragma unroll
        for (int j = 0; j < 4; j++) {
            int col = w * 32 + j * 8 + 2 * t;
            #pragma unroll
            for (int i2 = 0; i2 < 2; i2++) {
                int gr = n0 + mt * 16 + g + 8 * i2;
                float2 o;
                o.x = a2[mt][j][2 * i2]     * inv[mt][i2];
                o.y = a2[mt][j][2 * i2 + 1] * inv[mt][i2];
                *(float2*)&outg[(size_t)gr * 512 + 256 + col] = o;
            }
        }
}

extern "C" void kernel_launch(void* const* d_in, const int* in_sizes, int n_in,
                              void* d_out, int out_size) {
    const float* query      = (const float*)d_in[0];
    const float* mem_attr   = (const float*)d_in[1];
    const float* mem_struct = (const float*)d_in[2];
    float* out = (float*)d_out;

    prep_kernel<<<512, 256>>>(mem_attr, mem_struct);

    cudaFuncSetAttribute(smgt_hmma, cudaFuncAttributeMaxDynamicSharedMemorySize, SMEM_BYTES);
    dim3 grid(N_TILES, 2);
    smgt_hmma<<<grid, THREADS, SMEM_BYTES>>>(query, out);
}